// round 4
// baseline (speedup 1.0000x reference)
#include <cuda_runtime.h>
#include <math.h>

#define BATCH 2
#define DIM   48
#define HEADS 8
#define CPH   6
#define HH    384
#define WW    384
#define NPIX  (HH*WW)

// qk tile geometry
#define QTX 32
#define QTY 16
#define QHX 34
#define QHY 18
#define QST 36                 // padded smem row stride (floats)
#define QCH (QHY*QST)          // floats per channel plane (648)

// ---------------- scratch ----------------
__device__ float g_pwq [BATCH*DIM*NPIX];      // 56.6 MB
__device__ float g_pwkv[BATCH*2*DIM*NPIX];    // 113 MB (k: ch 0..47, v: ch 48..95)
__device__ float g_acc [BATCH*HEADS*48];      // 36 Gram + 6 |q|^2 + 6 |k|^2
__device__ float g_meff[BATCH*DIM*DIM];

// ---------------- packed f32x2 ----------------
__device__ __forceinline__ unsigned long long pk2(float lo, float hi){
    unsigned long long r;
    asm("mov.b64 %0, {%1,%2};" : "=l"(r) : "f"(lo), "f"(hi));
    return r;
}
__device__ __forceinline__ void fma2(unsigned long long &d,
                                     unsigned long long a,
                                     unsigned long long b){
    asm("fma.rn.f32x2 %0, %1, %2, %3;" : "=l"(d) : "l"(a), "l"(b), "l"(d));
}
__device__ __forceinline__ float2 unpk(unsigned long long v){
    float lo, hi;
    asm("mov.b64 {%0,%1}, %2;" : "=f"(lo), "=f"(hi) : "l"(v));
    return make_float2(lo, hi);
}

__device__ __forceinline__ void row3(float* r, const float* rowp, int x, int xl, int xr,
                                     bool xm, bool xp, bool yok){
    r[0] = (yok && xm) ? __ldg(rowp + xl) : 0.f;
    r[1] =  yok        ? __ldg(rowp + x ) : 0.f;
    r[2] = (yok && xp) ? __ldg(rowp + xr) : 0.f;
}

#define CONV9(s, w, a, b_, c) \
    s = w[0]*a[0]+w[1]*a[1]+w[2]*a[2] \
      + w[3]*b_[0]+w[4]*b_[1]+w[5]*b_[2] \
      + w[6]*c[0]+w[7]*c[1]+w[8]*c[2];

// ---------------- kernels ----------------
__global__ void zero_acc_kernel(){
    int t = blockIdx.x*blockDim.x + threadIdx.x;
    if (t < BATCH*HEADS*48) g_acc[t] = 0.f;
}

// 1x1 conv as GEMM, 48 oc, 256 px/block, direct LDG (round-2 config: fastest).
__global__ __launch_bounds__(256, 2) void pw48_kernel(const float* __restrict__ in,
                                                      const float* __restrict__ W,
                                                      float* __restrict__ out,
                                                      int inBC, int outBC){
    __shared__ unsigned long long ws[DIM*DIM];
    const int b = blockIdx.y;
    for (int t = threadIdx.x; t < DIM*DIM; t += 256){
        float w = W[t];
        ws[t] = pk2(w, w);
    }
    __syncthreads();

    const int tid = threadIdx.x;
    const int pxq = tid & 31;
    const int ocg = tid >> 5;
    const int base = blockIdx.x*256 + pxq*8;
    const float* inp = in + (size_t)b*inBC*NPIX + base;

    unsigned long long acc[CPH][4];
    #pragma unroll
    for (int j = 0; j < CPH; j++){
        acc[j][0]=0ull; acc[j][1]=0ull; acc[j][2]=0ull; acc[j][3]=0ull;
    }

    #pragma unroll 4
    for (int ic = 0; ic < DIM; ic++){
        const float4* ip4 = reinterpret_cast<const float4*>(inp + (size_t)ic*NPIX);
        float4 xa = ip4[0];
        float4 xb = ip4[1];
        unsigned long long a01 = pk2(xa.x, xa.y), a23 = pk2(xa.z, xa.w);
        unsigned long long b01 = pk2(xb.x, xb.y), b23 = pk2(xb.z, xb.w);
        #pragma unroll
        for (int j = 0; j < CPH; j++){
            unsigned long long w = ws[(ocg*CPH + j)*DIM + ic];
            fma2(acc[j][0], a01, w);
            fma2(acc[j][1], a23, w);
            fma2(acc[j][2], b01, w);
            fma2(acc[j][3], b23, w);
        }
    }

    float* op = out + (size_t)b*outBC*NPIX + base;
    #pragma unroll
    for (int j = 0; j < CPH; j++){
        float* o = op + (size_t)(ocg*CPH + j)*NPIX;
        float2 l0 = unpk(acc[j][0]), h0 = unpk(acc[j][1]);
        float2 l1 = unpk(acc[j][2]), h1 = unpk(acc[j][3]);
        *reinterpret_cast<float4*>(o)     = make_float4(l0.x, l0.y, h0.x, h0.y);
        *reinterpret_cast<float4*>(o + 4) = make_float4(l1.x, l1.y, h1.x, h1.y);
    }
}

// fused img pointwise: 96 oc in one pass (img read from DRAM once).
// 512 threads = 16 warps x 6 oc; 256 px/block, 8 px/thread.
__global__ __launch_bounds__(512, 1) void pw96_kernel(const float* __restrict__ in,
                                                      const float* __restrict__ W,
                                                      float* __restrict__ out){
    __shared__ unsigned long long ws[2*DIM*DIM];    // 36 KB
    const int b = blockIdx.y;
    for (int t = threadIdx.x; t < 2*DIM*DIM; t += 512){
        float w = W[t];
        ws[t] = pk2(w, w);
    }
    __syncthreads();

    const int tid = threadIdx.x;
    const int pxq = tid & 31;
    const int ocg = tid >> 5;        // 0..15
    const int base = blockIdx.x*256 + pxq*8;
    const float* inp = in + (size_t)b*DIM*NPIX + base;

    unsigned long long acc[CPH][4];
    #pragma unroll
    for (int j = 0; j < CPH; j++){
        acc[j][0]=0ull; acc[j][1]=0ull; acc[j][2]=0ull; acc[j][3]=0ull;
    }

    #pragma unroll 4
    for (int ic = 0; ic < DIM; ic++){
        const float4* ip4 = reinterpret_cast<const float4*>(inp + (size_t)ic*NPIX);
        float4 xa = ip4[0];
        float4 xb = ip4[1];
        unsigned long long a01 = pk2(xa.x, xa.y), a23 = pk2(xa.z, xa.w);
        unsigned long long b01 = pk2(xb.x, xb.y), b23 = pk2(xb.z, xb.w);
        #pragma unroll
        for (int j = 0; j < CPH; j++){
            unsigned long long w = ws[(ocg*CPH + j)*DIM + ic];
            fma2(acc[j][0], a01, w);
            fma2(acc[j][1], a23, w);
            fma2(acc[j][2], b01, w);
            fma2(acc[j][3], b23, w);
        }
    }

    float* op = out + (size_t)b*2*DIM*NPIX + base;
    #pragma unroll
    for (int j = 0; j < CPH; j++){
        float* o = op + (size_t)(ocg*CPH + j)*NPIX;
        float2 l0 = unpk(acc[j][0]), h0 = unpk(acc[j][1]);
        float2 l1 = unpk(acc[j][2]), h1 = unpk(acc[j][3]);
        *reinterpret_cast<float4*>(o)     = make_float4(l0.x, l0.y, h0.x, h0.y);
        *reinterpret_cast<float4*>(o + 4) = make_float4(l1.x, l1.y, h1.x, h1.y);
    }
}

// q,k depthwise 3x3 + Gram/norm. One (b,h) per block, 32x16 tile, smem halo staging.
// 8 warps: warp w owns output rows 2w, 2w+1 (all 32 x-columns).
__global__ __launch_bounds__(256, 2) void qk_gram_kernel(const float* __restrict__ Wq2,
                                                         const float* __restrict__ Wkv2){
    __shared__ float s[12*QCH];          // 12 ch x 18 x 36 floats = 31104 B
    __shared__ float wq[CPH*9], wk[CPH*9];
    __shared__ float accs[48];
    const int tid = threadIdx.x;
    const int bh  = blockIdx.z;
    const int b   = bh >> 3, h = bh & 7;
    if (tid < CPH*9){
        int c6 = tid/9, t = tid%9;
        wq[tid] = Wq2 [(h*CPH + c6)*27 + 9 + t];
        wk[tid] = Wkv2[(h*CPH + c6)*27 + 9 + t];
    }
    if (tid < 48) accs[tid] = 0.f;

    const int x0 = blockIdx.x*QTX;
    const int y0 = blockIdx.y*QTY;
    const float* qbase = g_pwq  + (size_t)b*DIM*NPIX   + (size_t)h*CPH*NPIX;
    const float* kbase = g_pwkv + (size_t)b*2*DIM*NPIX + (size_t)h*CPH*NPIX;

    // stage 12 channel planes (q: 0..5, k: 6..11) with zero-filled halo
    for (int e = tid; e < 12*QHY*QHX; e += 256){
        int ch  = e / (QHY*QHX);
        int rem = e % (QHY*QHX);
        int r   = rem / QHX;
        int c   = rem % QHX;
        int gy = y0 - 1 + r, gx = x0 - 1 + c;
        float v = 0.f;
        if (gy >= 0 && gy < HH && gx >= 0 && gx < WW){
            const float* p = (ch < 6) ? qbase + (size_t)ch*NPIX
                                      : kbase + (size_t)(ch-6)*NPIX;
            v = __ldg(p + (size_t)gy*WW + gx);
        }
        s[ch*QCH + r*QST + c] = v;
    }
    __syncthreads();

    const int lane = tid & 31;
    const int w    = tid >> 5;
    const int r0   = 2*w;                 // output row pair within tile

    float ka[CPH][2];
    float kn[CPH], qn[CPH], G[36];
    #pragma unroll
    for (int i = 0; i < 36; i++) G[i] = 0.f;

    const float* sk = s + 6*QCH;
    // ---- k channels ----
    #pragma unroll
    for (int c6 = 0; c6 < CPH; c6++){
        const float* sp = sk + c6*QCH + r0*QST + lane;
        float a0[3], a1[3], a2[3], a3[3];
        #pragma unroll
        for (int d = 0; d < 3; d++){
            a0[d] = sp[d];
            a1[d] = sp[QST + d];
            a2[d] = sp[2*QST + d];
            a3[d] = sp[3*QST + d];
        }
        float wr[9];
        #pragma unroll
        for (int t = 0; t < 9; t++) wr[t] = wk[c6*9 + t];
        float v0, v1;
        CONV9(v0, wr, a0, a1, a2);
        CONV9(v1, wr, a1, a2, a3);
        ka[c6][0] = v0; ka[c6][1] = v1;
        kn[c6] = v0*v0 + v1*v1;
    }
    // ---- q channels + Gram ----
    #pragma unroll
    for (int c6 = 0; c6 < CPH; c6++){
        const float* sp = s + c6*QCH + r0*QST + lane;
        float a0[3], a1[3], a2[3], a3[3];
        #pragma unroll
        for (int d = 0; d < 3; d++){
            a0[d] = sp[d];
            a1[d] = sp[QST + d];
            a2[d] = sp[2*QST + d];
            a3[d] = sp[3*QST + d];
        }
        float wr[9];
        #pragma unroll
        for (int t = 0; t < 9; t++) wr[t] = wq[c6*9 + t];
        float v0, v1;
        CONV9(v0, wr, a0, a1, a2);
        CONV9(v1, wr, a1, a2, a3);
        qn[c6] = v0*v0 + v1*v1;
        #pragma unroll
        for (int d6 = 0; d6 < CPH; d6++)
            G[c6*CPH + d6] += v0*ka[d6][0] + v1*ka[d6][1];
    }

    // ---- reduce ----
    #pragma unroll
    for (int j = 0; j < 36; j++){
        float v = G[j];
        #pragma unroll
        for (int o = 16; o; o >>= 1) v += __shfl_xor_sync(0xffffffffu, v, o);
        if (lane == 0) atomicAdd(&accs[j], v);
    }
    #pragma unroll
    for (int j = 0; j < CPH; j++){
        float v = qn[j];
        #pragma unroll
        for (int o = 16; o; o >>= 1) v += __shfl_xor_sync(0xffffffffu, v, o);
        if (lane == 0) atomicAdd(&accs[36 + j], v);
        float u = kn[j];
        #pragma unroll
        for (int o = 16; o; o >>= 1) u += __shfl_xor_sync(0xffffffffu, u, o);
        if (lane == 0) atomicAdd(&accs[42 + j], u);
    }
    __syncthreads();
    if (tid < 48) atomicAdd(&g_acc[(b*HEADS + h)*48 + tid], accs[tid]);
}

// softmax + fold Wout -> Meff[b] (48x48)
__global__ void attn_kernel(const float* __restrict__ Wout,
                            const float* __restrict__ temp){
    __shared__ float attn_s[BATCH*HEADS*36];
    int t = threadIdx.x;
    if (t < BATCH*HEADS*CPH){
        int b  = t/(HEADS*CPH);
        int h  = (t/CPH)%HEADS;
        int c6 = t%CPH;
        const float* a = g_acc + (b*HEADS + h)*48;
        float qnorm = fmaxf(sqrtf(a[36 + c6]), 1e-12f);
        float s[CPH];
        float mx = -1e30f;
        #pragma unroll
        for (int d6 = 0; d6 < CPH; d6++){
            float knorm = fmaxf(sqrtf(a[42 + d6]), 1e-12f);
            float v = a[c6*CPH + d6] / (qnorm*knorm) * temp[h];
            s[d6] = v; mx = fmaxf(mx, v);
        }
        float sum = 0.f;
        #pragma unroll
        for (int d6 = 0; d6 < CPH; d6++){ s[d6] = expf(s[d6]-mx); sum += s[d6]; }
        float inv = 1.f/sum;
        #pragma unroll
        for (int d6 = 0; d6 < CPH; d6++)
            attn_s[(b*HEADS + h)*36 + c6*CPH + d6] = s[d6]*inv;
    }
    __syncthreads();
    for (int e = t; e < BATCH*DIM*DIM; e += blockDim.x){
        int b = e/(DIM*DIM), rem = e%(DIM*DIM), o = rem/DIM, d = rem%DIM;
        int h = d/CPH, d6 = d%CPH;
        float s = 0.f;
        #pragma unroll
        for (int c6 = 0; c6 < CPH; c6++)
            s += Wout[o*DIM + h*CPH + c6] * attn_s[(b*HEADS + h)*36 + c6*CPH + d6];
        g_meff[e] = s;
    }
}

// fused: v = dw3x3(pwkv_hi) into smem tile, then out = Meff[b] * v.
__global__ __launch_bounds__(256, 2) void vout_kernel(const float* __restrict__ Wkv2,
                                                      float* __restrict__ out){
    extern __shared__ char smraw[];
    unsigned long long* wm = reinterpret_cast<unsigned long long*>(smraw);      // 48*48 u64
    float* v_s = reinterpret_cast<float*>(smraw + DIM*DIM*8);                   // 48*256 f32
    float* wv  = v_s + DIM*256;                                                 // 48*9 f32

    const int tid = threadIdx.x;
    const int b   = blockIdx.z;
    for (int t = tid; t < DIM*DIM; t += 256){
        float m = g_meff[b*DIM*DIM + t];
        wm[t] = pk2(m, m);
    }
    for (int t = tid; t < DIM*9; t += 256)
        wv[t] = Wkv2[(DIM + t/9)*27 + 9 + (t%9)];
    __syncthreads();

    const int lane = tid & 31;
    const int w    = tid >> 5;
    const int x0   = blockIdx.x*32;
    const int x    = x0 + lane;
    const int yb   = blockIdx.y*8;
    const int  xl = max(x-1, 0), xr = min(x+1, WW-1);
    const bool xm = (x > 0),     xp = (x < WW-1);

    const float* vbase = g_pwkv + (size_t)b*2*DIM*NPIX + (size_t)DIM*NPIX;
    #pragma unroll
    for (int c6 = 0; c6 < CPH; c6++){
        int c = w*CPH + c6;
        const float* p = vbase + (size_t)c*NPIX;
        float wr[9];
        #pragma unroll
        for (int t = 0; t < 9; t++) wr[t] = wv[c*9 + t];
        float r0[3], r1[3], r2[3];
        { bool yok = (yb-1 >= 0); row3(r0, p + (yok ? (yb-1) : 0)*WW, x, xl, xr, xm, xp, yok); }
        row3(r1, p + yb*WW, x, xl, xr, xm, xp, true);
        #pragma unroll
        for (int i = 0; i < 8; i++){
            int yy = yb + i + 1; bool yok = (yy < HH);
            row3(r2, p + (yok ? yy : 0)*WW, x, xl, xr, xm, xp, yok);
            float s; CONV9(s, wr, r0, r1, r2);
            v_s[c*256 + i*32 + lane] = s;
            r0[0]=r1[0]; r0[1]=r1[1]; r0[2]=r1[2];
            r1[0]=r2[0]; r1[1]=r2[1]; r1[2]=r2[2];
        }
    }
    __syncthreads();

    unsigned long long acc[CPH][4];
    #pragma unroll
    for (int j = 0; j < CPH; j++){
        acc[j][0]=0ull; acc[j][1]=0ull; acc[j][2]=0ull; acc[j][3]=0ull;
    }
    #pragma unroll 4
    for (int d = 0; d < DIM; d++){
        const float4* vp = reinterpret_cast<const float4*>(v_s + d*256);
        float4 a  = vp[lane];
        float4 bq = vp[lane + 32];
        unsigned long long a01 = pk2(a.x,  a.y ), a23 = pk2(a.z,  a.w );
        unsigned long long b01 = pk2(bq.x, bq.y), b23 = pk2(bq.z, bq.w);
        #pragma unroll
        for (int j = 0; j < CPH; j++){
            unsigned long long ww = wm[(w*CPH + j)*DIM + d];
            fma2(acc[j][0], a01, ww);
            fma2(acc[j][1], a23, ww);
            fma2(acc[j][2], b01, ww);
            fma2(acc[j][3], b23, ww);
        }
    }

    #pragma unroll
    for (int j = 0; j < CPH; j++){
        int oc = w*CPH + j;
        float* op = out + ((size_t)(b*DIM + oc))*NPIX;
        int px0 = 4*lane;
        int px1 = 128 + 4*lane;
        float2 l0 = unpk(acc[j][0]), h0 = unpk(acc[j][1]);
        float2 l1 = unpk(acc[j][2]), h1 = unpk(acc[j][3]);
        *reinterpret_cast<float4*>(op + (size_t)(yb + (px0>>5))*WW + x0 + (px0&31)) =
            make_float4(l0.x, l0.y, h0.x, h0.y);
        *reinterpret_cast<float4*>(op + (size_t)(yb + (px1>>5))*WW + x0 + (px1&31)) =
            make_float4(l1.x, l1.y, h1.x, h1.y);
    }
}

// ---------------- launch ----------------
extern "C" void kernel_launch(void* const* d_in, const int* in_sizes, int n_in,
                              void* d_out, int out_size){
    const float* img  = (const float*)d_in[0];
    const float* evs  = (const float*)d_in[1];
    const float* Wq1  = (const float*)d_in[2];
    const float* Wq2  = (const float*)d_in[3];
    const float* Wkv1 = (const float*)d_in[4];
    const float* Wkv2 = (const float*)d_in[5];
    const float* Wout = (const float*)d_in[6];
    const float* temp = (const float*)d_in[7];
    float* out = (float*)d_out;

    float *pwq, *pwkv;
    cudaGetSymbolAddress((void**)&pwq,  g_pwq);
    cudaGetSymbolAddress((void**)&pwkv, g_pwkv);

    size_t smem_vout = (size_t)DIM*DIM*8 + (size_t)DIM*256*4 + (size_t)DIM*9*4; // 69312
    cudaFuncSetAttribute(vout_kernel, cudaFuncAttributeMaxDynamicSharedMemorySize, (int)smem_vout);

    zero_acc_kernel<<<3, 256>>>();

    dim3 gpw(NPIX/256, BATCH);
    pw48_kernel<<<gpw, 256>>>(evs, Wq1, pwq, DIM, DIM);
    pw96_kernel<<<gpw, 512>>>(img, Wkv1, pwkv);

    dim3 gqk(WW/QTX, HH/QTY, BATCH*HEADS);
    qk_gram_kernel<<<gqk, 256>>>(Wq2, Wkv2);

    attn_kernel<<<1, 256>>>(Wout, temp);

    dim3 gvo(WW/32, HH/8, BATCH);
    vout_kernel<<<gvo, 256, smem_vout>>>(Wkv2, out);
}

// round 5
// speedup vs baseline: 1.9706x; 1.9706x over previous
#include <cuda_runtime.h>
#include <math.h>

#define BATCH 2
#define DIM   48
#define HEADS 8
#define CPH   6
#define HH    384
#define WW    384
#define NPIX  (HH*WW)

// ---------------- scratch ----------------
__device__ float g_pwq [BATCH*DIM*NPIX];      // 56.6 MB
__device__ float g_pwkv[BATCH*2*DIM*NPIX];    // 113 MB (k: ch 0..47, v: ch 48..95)
__device__ float g_acc [BATCH*HEADS*48];      // 36 Gram + 6 |q|^2 + 6 |k|^2
__device__ float g_meff[BATCH*DIM*DIM];

// ---------------- packed f32x2 ----------------
__device__ __forceinline__ unsigned long long pk2(float lo, float hi){
    unsigned long long r;
    asm("mov.b64 %0, {%1,%2};" : "=l"(r) : "f"(lo), "f"(hi));
    return r;
}
__device__ __forceinline__ void fma2(unsigned long long &d,
                                     unsigned long long a,
                                     unsigned long long b){
    asm("fma.rn.f32x2 %0, %1, %2, %3;" : "=l"(d) : "l"(a), "l"(b), "l"(d));
}
__device__ __forceinline__ float2 unpk(unsigned long long v){
    float lo, hi;
    asm("mov.b64 {%0,%1}, %2;" : "=f"(lo), "=f"(hi) : "l"(v));
    return make_float2(lo, hi);
}

// Load an R-row x 3-col window upfront (independent LDGs, MLP=3R) and produce
// R-2 conv outputs. fast => no bounds handling (interior block).
template<int R>
__device__ __forceinline__ void winconv(const float* __restrict__ chan, int x,
                                        bool xm, bool xp, int ytop, bool fast,
                                        const float* __restrict__ wr, float* out){
    float v[R][3];
    if (fast){
        const float* rp = chan + (size_t)ytop*WW + x;
        #pragma unroll
        for (int r = 0; r < R; r++){
            v[r][0] = __ldg(rp + r*WW - 1);
            v[r][1] = __ldg(rp + r*WW    );
            v[r][2] = __ldg(rp + r*WW + 1);
        }
    } else {
        int xl = max(x-1, 0), xr = min(x+1, WW-1);
        #pragma unroll
        for (int r = 0; r < R; r++){
            int yy = ytop + r; bool yok = (yy >= 0 && yy < HH);
            const float* rp = chan + (size_t)(yok ? yy : 0)*WW;
            v[r][0] = (yok && xm) ? __ldg(rp + xl) : 0.f;
            v[r][1] =  yok        ? __ldg(rp + x ) : 0.f;
            v[r][2] = (yok && xp) ? __ldg(rp + xr) : 0.f;
        }
    }
    #pragma unroll
    for (int i = 0; i < R-2; i++){
        out[i] = wr[0]*v[i  ][0] + wr[1]*v[i  ][1] + wr[2]*v[i  ][2]
               + wr[3]*v[i+1][0] + wr[4]*v[i+1][1] + wr[5]*v[i+1][2]
               + wr[6]*v[i+2][0] + wr[7]*v[i+2][1] + wr[8]*v[i+2][2];
    }
}

// ---------------- kernels ----------------
__global__ void zero_acc_kernel(){
    int t = blockIdx.x*blockDim.x + threadIdx.x;
    if (t < BATCH*HEADS*48) g_acc[t] = 0.f;
}

// 1x1 conv as GEMM, 48 oc, 256 px/block, direct LDG.
__global__ __launch_bounds__(256, 2) void pw48_kernel(const float* __restrict__ in,
                                                      const float* __restrict__ W,
                                                      float* __restrict__ out,
                                                      int inBC, int outBC){
    __shared__ unsigned long long ws[DIM*DIM];
    const int b = blockIdx.y;
    for (int t = threadIdx.x; t < DIM*DIM; t += 256){
        float w = W[t];
        ws[t] = pk2(w, w);
    }
    __syncthreads();

    const int tid = threadIdx.x;
    const int pxq = tid & 31;
    const int ocg = tid >> 5;
    const int base = blockIdx.x*256 + pxq*8;
    const float* inp = in + (size_t)b*inBC*NPIX + base;

    unsigned long long acc[CPH][4];
    #pragma unroll
    for (int j = 0; j < CPH; j++){
        acc[j][0]=0ull; acc[j][1]=0ull; acc[j][2]=0ull; acc[j][3]=0ull;
    }

    #pragma unroll 4
    for (int ic = 0; ic < DIM; ic++){
        const float4* ip4 = reinterpret_cast<const float4*>(inp + (size_t)ic*NPIX);
        float4 xa = ip4[0];
        float4 xb = ip4[1];
        unsigned long long a01 = pk2(xa.x, xa.y), a23 = pk2(xa.z, xa.w);
        unsigned long long b01 = pk2(xb.x, xb.y), b23 = pk2(xb.z, xb.w);
        #pragma unroll
        for (int j = 0; j < CPH; j++){
            unsigned long long w = ws[(ocg*CPH + j)*DIM + ic];
            fma2(acc[j][0], a01, w);
            fma2(acc[j][1], a23, w);
            fma2(acc[j][2], b01, w);
            fma2(acc[j][3], b23, w);
        }
    }

    float* op = out + (size_t)b*outBC*NPIX + base;
    #pragma unroll
    for (int j = 0; j < CPH; j++){
        float* o = op + (size_t)(ocg*CPH + j)*NPIX;
        float2 l0 = unpk(acc[j][0]), h0 = unpk(acc[j][1]);
        float2 l1 = unpk(acc[j][2]), h1 = unpk(acc[j][3]);
        *reinterpret_cast<float4*>(o)     = make_float4(l0.x, l0.y, h0.x, h0.y);
        *reinterpret_cast<float4*>(o + 4) = make_float4(l1.x, l1.y, h1.x, h1.y);
    }
}

// fused img pointwise: 96 oc in one pass (img read from DRAM once).
__global__ __launch_bounds__(512, 1) void pw96_kernel(const float* __restrict__ in,
                                                      const float* __restrict__ W,
                                                      float* __restrict__ out){
    __shared__ unsigned long long ws[2*DIM*DIM];
    const int b = blockIdx.y;
    for (int t = threadIdx.x; t < 2*DIM*DIM; t += 512){
        float w = W[t];
        ws[t] = pk2(w, w);
    }
    __syncthreads();

    const int tid = threadIdx.x;
    const int pxq = tid & 31;
    const int ocg = tid >> 5;
    const int base = blockIdx.x*256 + pxq*8;
    const float* inp = in + (size_t)b*DIM*NPIX + base;

    unsigned long long acc[CPH][4];
    #pragma unroll
    for (int j = 0; j < CPH; j++){
        acc[j][0]=0ull; acc[j][1]=0ull; acc[j][2]=0ull; acc[j][3]=0ull;
    }

    #pragma unroll 4
    for (int ic = 0; ic < DIM; ic++){
        const float4* ip4 = reinterpret_cast<const float4*>(inp + (size_t)ic*NPIX);
        float4 xa = ip4[0];
        float4 xb = ip4[1];
        unsigned long long a01 = pk2(xa.x, xa.y), a23 = pk2(xa.z, xa.w);
        unsigned long long b01 = pk2(xb.x, xb.y), b23 = pk2(xb.z, xb.w);
        #pragma unroll
        for (int j = 0; j < CPH; j++){
            unsigned long long w = ws[(ocg*CPH + j)*DIM + ic];
            fma2(acc[j][0], a01, w);
            fma2(acc[j][1], a23, w);
            fma2(acc[j][2], b01, w);
            fma2(acc[j][3], b23, w);
        }
    }

    float* op = out + (size_t)b*2*DIM*NPIX + base;
    #pragma unroll
    for (int j = 0; j < CPH; j++){
        float* o = op + (size_t)(ocg*CPH + j)*NPIX;
        float2 l0 = unpk(acc[j][0]), h0 = unpk(acc[j][1]);
        float2 l1 = unpk(acc[j][2]), h1 = unpk(acc[j][3]);
        *reinterpret_cast<float4*>(o)     = make_float4(l0.x, l0.y, h0.x, h0.y);
        *reinterpret_cast<float4*>(o + 4) = make_float4(l1.x, l1.y, h1.x, h1.y);
    }
}

// q,k depthwise 3x3 + Gram/norm. One (b,h) per block; block covers 32x128 px.
// Warp w owns output rows w*4..w*4+3 in each of 4 y-iterations; G/norms persist
// in registers across iterations; ONE reduce per block.
__global__ __launch_bounds__(256, 2) void qk_gram_kernel(const float* __restrict__ Wq2,
                                                         const float* __restrict__ Wkv2){
    __shared__ float wq[CPH*9], wk[CPH*9];
    __shared__ float accs[48];
    const int tid = threadIdx.x;
    const int bh  = blockIdx.z;
    const int b   = bh >> 3, h = bh & 7;
    if (tid < CPH*9){
        int c6 = tid/9, t = tid%9;
        wq[tid] = Wq2[(h*CPH + c6)*27 + 9 + t];
    } else if (tid >= 64 && tid < 64 + CPH*9){
        int e = tid - 64, c6 = e/9, t = e%9;
        wk[e] = Wkv2[(h*CPH + c6)*27 + 9 + t];
    } else if (tid >= 128 && tid < 176){
        accs[tid - 128] = 0.f;
    }
    __syncthreads();

    const int lane = tid & 31;
    const int w    = tid >> 5;
    const int x0   = blockIdx.x*32;
    const int x    = x0 + lane;
    const bool xm = (x > 0), xp = (x < WW-1);
    const bool xfast = (x0 > 0) && (x0 + 32 < WW);

    const float* qbase = g_pwq  + (size_t)b*DIM*NPIX   + (size_t)h*CPH*NPIX;
    const float* kbase = g_pwkv + (size_t)b*2*DIM*NPIX + (size_t)h*CPH*NPIX;

    float G[36], qn[CPH], kn[CPH];
    #pragma unroll
    for (int i = 0; i < 36; i++) G[i] = 0.f;
    #pragma unroll
    for (int i = 0; i < CPH; i++){ qn[i] = 0.f; kn[i] = 0.f; }

    #pragma unroll 1
    for (int t4 = 0; t4 < 4; t4++){
        const int y0   = blockIdx.y*128 + t4*32 + w*4;
        const int ytop = y0 - 1;
        const bool fast = xfast && (ytop >= 0) && (ytop + 5 < HH);

        float ka[CPH][4];
        #pragma unroll
        for (int c6 = 0; c6 < CPH; c6++){
            float o[4];
            winconv<6>(kbase + (size_t)c6*NPIX, x, xm, xp, ytop, fast, &wk[c6*9], o);
            #pragma unroll
            for (int i = 0; i < 4; i++){ ka[c6][i] = o[i]; kn[c6] += o[i]*o[i]; }
        }
        #pragma unroll
        for (int c6 = 0; c6 < CPH; c6++){
            float o[4];
            winconv<6>(qbase + (size_t)c6*NPIX, x, xm, xp, ytop, fast, &wq[c6*9], o);
            #pragma unroll
            for (int i = 0; i < 4; i++) qn[c6] += o[i]*o[i];
            #pragma unroll
            for (int d6 = 0; d6 < CPH; d6++)
                G[c6*CPH + d6] += o[0]*ka[d6][0] + o[1]*ka[d6][1]
                                + o[2]*ka[d6][2] + o[3]*ka[d6][3];
        }
    }

    // ---- reduce: one per block ----
    #pragma unroll
    for (int j = 0; j < 36; j++){
        float v = G[j];
        #pragma unroll
        for (int o = 16; o; o >>= 1) v += __shfl_xor_sync(0xffffffffu, v, o);
        if (lane == 0) atomicAdd(&accs[j], v);
    }
    #pragma unroll
    for (int j = 0; j < CPH; j++){
        float v = qn[j];
        #pragma unroll
        for (int o = 16; o; o >>= 1) v += __shfl_xor_sync(0xffffffffu, v, o);
        if (lane == 0) atomicAdd(&accs[36 + j], v);
        float u = kn[j];
        #pragma unroll
        for (int o = 16; o; o >>= 1) u += __shfl_xor_sync(0xffffffffu, u, o);
        if (lane == 0) atomicAdd(&accs[42 + j], u);
    }
    __syncthreads();
    if (tid < 48) atomicAdd(&g_acc[(b*HEADS + h)*48 + tid], accs[tid]);
}

// softmax + fold Wout -> Meff[b] (48x48)
__global__ void attn_kernel(const float* __restrict__ Wout,
                            const float* __restrict__ temp){
    __shared__ float attn_s[BATCH*HEADS*36];
    int t = threadIdx.x;
    if (t < BATCH*HEADS*CPH){
        int b  = t/(HEADS*CPH);
        int h  = (t/CPH)%HEADS;
        int c6 = t%CPH;
        const float* a = g_acc + (b*HEADS + h)*48;
        float qnorm = fmaxf(sqrtf(a[36 + c6]), 1e-12f);
        float s[CPH];
        float mx = -1e30f;
        #pragma unroll
        for (int d6 = 0; d6 < CPH; d6++){
            float knorm = fmaxf(sqrtf(a[42 + d6]), 1e-12f);
            float v = a[c6*CPH + d6] / (qnorm*knorm) * temp[h];
            s[d6] = v; mx = fmaxf(mx, v);
        }
        float sum = 0.f;
        #pragma unroll
        for (int d6 = 0; d6 < CPH; d6++){ s[d6] = expf(s[d6]-mx); sum += s[d6]; }
        float inv = 1.f/sum;
        #pragma unroll
        for (int d6 = 0; d6 < CPH; d6++)
            attn_s[(b*HEADS + h)*36 + c6*CPH + d6] = s[d6]*inv;
    }
    __syncthreads();
    for (int e = t; e < BATCH*DIM*DIM; e += blockDim.x){
        int b = e/(DIM*DIM), rem = e%(DIM*DIM), o = rem/DIM, d = rem%DIM;
        int h = d/CPH, d6 = d%CPH;
        float s = 0.f;
        #pragma unroll
        for (int c6 = 0; c6 < CPH; c6++)
            s += Wout[o*DIM + h*CPH + c6] * attn_s[(b*HEADS + h)*36 + c6*CPH + d6];
        g_meff[e] = s;
    }
}

// fused: v = dw3x3(pwkv_hi) into smem tile (upfront-window loads), then out = Meff[b] * v.
__global__ __launch_bounds__(256, 2) void vout_kernel(const float* __restrict__ Wkv2,
                                                      float* __restrict__ out){
    extern __shared__ char smraw[];
    unsigned long long* wm = reinterpret_cast<unsigned long long*>(smraw);      // 48*48 u64
    float* v_s = reinterpret_cast<float*>(smraw + DIM*DIM*8);                   // 48*256 f32
    float* wv  = v_s + DIM*256;                                                 // 48*9 f32

    const int tid = threadIdx.x;
    const int b   = blockIdx.z;
    for (int t = tid; t < DIM*DIM; t += 256){
        float m = g_meff[b*DIM*DIM + t];
        wm[t] = pk2(m, m);
    }
    for (int t = tid; t < DIM*9; t += 256)
        wv[t] = Wkv2[(DIM + t/9)*27 + 9 + (t%9)];
    __syncthreads();

    const int lane = tid & 31;
    const int w    = tid >> 5;
    const int x0   = blockIdx.x*32;
    const int x    = x0 + lane;
    const int yb   = blockIdx.y*8;
    const bool xm = (x > 0), xp = (x < WW-1);
    const bool fast = (x0 > 0) && (x0 + 32 < WW) && (yb > 0) && (yb + 9 < HH);

    const float* vbase = g_pwkv + (size_t)b*2*DIM*NPIX + (size_t)DIM*NPIX;
    #pragma unroll
    for (int c6 = 0; c6 < CPH; c6++){
        int c = w*CPH + c6;
        float o[8];
        winconv<10>(vbase + (size_t)c*NPIX, x, xm, xp, yb - 1, fast, &wv[c*9], o);
        #pragma unroll
        for (int i = 0; i < 8; i++)
            v_s[c*256 + i*32 + lane] = o[i];
    }
    __syncthreads();

    unsigned long long acc[CPH][4];
    #pragma unroll
    for (int j = 0; j < CPH; j++){
        acc[j][0]=0ull; acc[j][1]=0ull; acc[j][2]=0ull; acc[j][3]=0ull;
    }
    #pragma unroll 4
    for (int d = 0; d < DIM; d++){
        const float4* vp = reinterpret_cast<const float4*>(v_s + d*256);
        float4 a  = vp[lane];
        float4 bq = vp[lane + 32];
        unsigned long long a01 = pk2(a.x,  a.y ), a23 = pk2(a.z,  a.w );
        unsigned long long b01 = pk2(bq.x, bq.y), b23 = pk2(bq.z, bq.w);
        #pragma unroll
        for (int j = 0; j < CPH; j++){
            unsigned long long ww = wm[(w*CPH + j)*DIM + d];
            fma2(acc[j][0], a01, ww);
            fma2(acc[j][1], a23, ww);
            fma2(acc[j][2], b01, ww);
            fma2(acc[j][3], b23, ww);
        }
    }

    #pragma unroll
    for (int j = 0; j < CPH; j++){
        int oc = w*CPH + j;
        float* op = out + ((size_t)(b*DIM + oc))*NPIX;
        int px0 = 4*lane;
        int px1 = 128 + 4*lane;
        float2 l0 = unpk(acc[j][0]), h0 = unpk(acc[j][1]);
        float2 l1 = unpk(acc[j][2]), h1 = unpk(acc[j][3]);
        *reinterpret_cast<float4*>(op + (size_t)(yb + (px0>>5))*WW + x0 + (px0&31)) =
            make_float4(l0.x, l0.y, h0.x, h0.y);
        *reinterpret_cast<float4*>(op + (size_t)(yb + (px1>>5))*WW + x0 + (px1&31)) =
            make_float4(l1.x, l1.y, h1.x, h1.y);
    }
}

// ---------------- launch ----------------
extern "C" void kernel_launch(void* const* d_in, const int* in_sizes, int n_in,
                              void* d_out, int out_size){
    const float* img  = (const float*)d_in[0];
    const float* evs  = (const float*)d_in[1];
    const float* Wq1  = (const float*)d_in[2];
    const float* Wq2  = (const float*)d_in[3];
    const float* Wkv1 = (const float*)d_in[4];
    const float* Wkv2 = (const float*)d_in[5];
    const float* Wout = (const float*)d_in[6];
    const float* temp = (const float*)d_in[7];
    float* out = (float*)d_out;

    float *pwq, *pwkv;
    cudaGetSymbolAddress((void**)&pwq,  g_pwq);
    cudaGetSymbolAddress((void**)&pwkv, g_pwkv);

    size_t smem_vout = (size_t)DIM*DIM*8 + (size_t)DIM*256*4 + (size_t)DIM*9*4; // 69312
    cudaFuncSetAttribute(vout_kernel, cudaFuncAttributeMaxDynamicSharedMemorySize, (int)smem_vout);

    zero_acc_kernel<<<3, 256>>>();

    dim3 gpw(NPIX/256, BATCH);
    pw48_kernel<<<gpw, 256>>>(evs, Wq1, pwq, DIM, DIM);
    pw96_kernel<<<gpw, 512>>>(img, Wkv1, pwkv);

    dim3 gqk(WW/32, HH/128, BATCH*HEADS);
    qk_gram_kernel<<<gqk, 256>>>(Wq2, Wkv2);

    attn_kernel<<<1, 256>>>(Wout, temp);

    dim3 gvo(WW/32, HH/8, BATCH);
    vout_kernel<<<gvo, 256, smem_vout>>>(Wkv2, out);
}

// round 6
// speedup vs baseline: 2.2661x; 1.1500x over previous
#include <cuda_runtime.h>
#include <math.h>

#define BATCH 2
#define DIM   48
#define HEADS 8
#define CPH   6
#define HH    384
#define WW    384
#define NPIX  (HH*WW)

// ---------------- scratch ----------------
__device__ float g_pwq [BATCH*DIM*NPIX];      // 56.6 MB
__device__ float g_pwkv[BATCH*2*DIM*NPIX];    // 113 MB (k: ch 0..47, v: ch 48..95)
__device__ float g_acc [BATCH*HEADS*48];      // 36 Gram + 6 |q|^2 + 6 |k|^2
__device__ float g_meff[BATCH*DIM*DIM];

// ---------------- packed f32x2 ----------------
__device__ __forceinline__ unsigned long long pk2(float lo, float hi){
    unsigned long long r;
    asm("mov.b64 %0, {%1,%2};" : "=l"(r) : "f"(lo), "f"(hi));
    return r;
}
__device__ __forceinline__ void fma2(unsigned long long &d,
                                     unsigned long long a,
                                     unsigned long long b){
    asm("fma.rn.f32x2 %0, %1, %2, %3;" : "=l"(d) : "l"(a), "l"(b), "l"(d));
}
__device__ __forceinline__ float2 unpk(unsigned long long v){
    float lo, hi;
    asm("mov.b64 {%0,%1}, %2;" : "=f"(lo), "=f"(hi) : "l"(v));
    return make_float2(lo, hi);
}

__device__ __forceinline__ void cpa16(unsigned int dst, const float* src){
    asm volatile("cp.async.cg.shared.global [%0], [%1], 16;" :: "r"(dst), "l"(src) : "memory");
}
__device__ __forceinline__ void cpa_commit(){
    asm volatile("cp.async.commit_group;" ::: "memory");
}
template<int N>
__device__ __forceinline__ void cpa_wait(){
    asm volatile("cp.async.wait_group %0;" :: "n"(N) : "memory");
}

// Load an R-row x 3-col window upfront (independent LDGs, MLP=3R) and produce
// R-2 conv outputs. fast => no bounds handling (interior block).
template<int R>
__device__ __forceinline__ void winconv(const float* __restrict__ chan, int x,
                                        bool xm, bool xp, int ytop, bool fast,
                                        const float* __restrict__ wr, float* out){
    float v[R][3];
    if (fast){
        const float* rp = chan + (size_t)ytop*WW + x;
        #pragma unroll
        for (int r = 0; r < R; r++){
            v[r][0] = __ldg(rp + r*WW - 1);
            v[r][1] = __ldg(rp + r*WW    );
            v[r][2] = __ldg(rp + r*WW + 1);
        }
    } else {
        int xl = max(x-1, 0), xr = min(x+1, WW-1);
        #pragma unroll
        for (int r = 0; r < R; r++){
            int yy = ytop + r; bool yok = (yy >= 0 && yy < HH);
            const float* rp = chan + (size_t)(yok ? yy : 0)*WW;
            v[r][0] = (yok && xm) ? __ldg(rp + xl) : 0.f;
            v[r][1] =  yok        ? __ldg(rp + x ) : 0.f;
            v[r][2] = (yok && xp) ? __ldg(rp + xr) : 0.f;
        }
    }
    #pragma unroll
    for (int i = 0; i < R-2; i++){
        out[i] = wr[0]*v[i  ][0] + wr[1]*v[i  ][1] + wr[2]*v[i  ][2]
               + wr[3]*v[i+1][0] + wr[4]*v[i+1][1] + wr[5]*v[i+1][2]
               + wr[6]*v[i+2][0] + wr[7]*v[i+2][1] + wr[8]*v[i+2][2];
    }
}

// ---------------- kernels ----------------
__global__ void zero_acc_kernel(){
    int t = blockIdx.x*blockDim.x + threadIdx.x;
    if (t < BATCH*HEADS*48) g_acc[t] = 0.f;
}

// 1x1 conv as GEMM with cp.async double-buffered input staging.
// Block: 256 threads, 256 px, 48 oc (oc-half selected by blockIdx.z).
// 8 warps x 6 oc, 8 px/thread via FFMA2. Input chunks of 8 ic (8KB/stage).
__global__ __launch_bounds__(256, 2) void pw_cp_kernel(const float* __restrict__ in,
                                                       const float* __restrict__ W,
                                                       float* __restrict__ out,
                                                       int inBC, int outBC){
    __shared__ unsigned long long ws[DIM*DIM];   // 18 KB
    __shared__ float xs[2][8*256];               // 16 KB

    const int b  = blockIdx.y;
    const int zh = blockIdx.z;                   // oc half
    const float* Wb = W + zh*DIM*DIM;
    for (int t = threadIdx.x; t < DIM*DIM; t += 256){
        float w = Wb[t];
        ws[t] = pk2(w, w);
    }

    const int tid  = threadIdx.x;
    const int base = blockIdx.x*256;
    const float* inp = in + (size_t)b*inBC*NPIX + base;
    const unsigned int xsu =
        (unsigned int)__cvta_generic_to_shared(&xs[0][0]);

    // issue chunk c into buffer buf: 512 float4, 2 per thread
    auto issue = [&](int c, int buf){
        #pragma unroll
        for (int r = 0; r < 2; r++){
            int e   = tid + r*256;
            int icl = e >> 6;
            int q   = e & 63;
            cpa16(xsu + (unsigned int)((buf*2048 + icl*256 + q*4)*4),
                  inp + (size_t)(c*8 + icl)*NPIX + q*4);
        }
        cpa_commit();
    };

    issue(0, 0);

    const int pxq = tid & 31;
    const int ocg = tid >> 5;

    unsigned long long acc[CPH][4];
    #pragma unroll
    for (int j = 0; j < CPH; j++){
        acc[j][0]=0ull; acc[j][1]=0ull; acc[j][2]=0ull; acc[j][3]=0ull;
    }

    #pragma unroll
    for (int c = 0; c < 6; c++){
        if (c < 5) issue(c+1, (c+1)&1);
        if (c < 5) cpa_wait<1>(); else cpa_wait<0>();
        __syncthreads();

        const float* xb = &xs[c&1][0];
        #pragma unroll
        for (int icl = 0; icl < 8; icl++){
            const float4* xp = reinterpret_cast<const float4*>(xb + icl*256 + pxq*8);
            float4 xa = xp[0];
            float4 xc = xp[1];
            unsigned long long a01 = pk2(xa.x, xa.y), a23 = pk2(xa.z, xa.w);
            unsigned long long b01 = pk2(xc.x, xc.y), b23 = pk2(xc.z, xc.w);
            #pragma unroll
            for (int j = 0; j < CPH; j++){
                unsigned long long w = ws[(ocg*CPH + j)*DIM + c*8 + icl];
                fma2(acc[j][0], a01, w);
                fma2(acc[j][1], a23, w);
                fma2(acc[j][2], b01, w);
                fma2(acc[j][3], b23, w);
            }
        }
        __syncthreads();
    }

    float* op = out + (size_t)b*outBC*NPIX + base + pxq*8;
    #pragma unroll
    for (int j = 0; j < CPH; j++){
        float* o = op + (size_t)(zh*DIM + ocg*CPH + j)*NPIX;
        float2 l0 = unpk(acc[j][0]), h0 = unpk(acc[j][1]);
        float2 l1 = unpk(acc[j][2]), h1 = unpk(acc[j][3]);
        *reinterpret_cast<float4*>(o)     = make_float4(l0.x, l0.y, h0.x, h0.y);
        *reinterpret_cast<float4*>(o + 4) = make_float4(l1.x, l1.y, h1.x, h1.y);
    }
}

// q,k depthwise 3x3 + Gram/norm. One (b,h) per block; block covers 32x128 px.
__global__ __launch_bounds__(256, 2) void qk_gram_kernel(const float* __restrict__ Wq2,
                                                         const float* __restrict__ Wkv2){
    __shared__ float wq[CPH*9], wk[CPH*9];
    __shared__ float accs[48];
    const int tid = threadIdx.x;
    const int bh  = blockIdx.z;
    const int b   = bh >> 3, h = bh & 7;
    if (tid < CPH*9){
        int c6 = tid/9, t = tid%9;
        wq[tid] = Wq2[(h*CPH + c6)*27 + 9 + t];
    } else if (tid >= 64 && tid < 64 + CPH*9){
        int e = tid - 64, c6 = e/9, t = e%9;
        wk[e] = Wkv2[(h*CPH + c6)*27 + 9 + t];
    } else if (tid >= 128 && tid < 176){
        accs[tid - 128] = 0.f;
    }
    __syncthreads();

    const int lane = tid & 31;
    const int w    = tid >> 5;
    const int x0   = blockIdx.x*32;
    const int x    = x0 + lane;
    const bool xm = (x > 0), xp = (x < WW-1);
    const bool xfast = (x0 > 0) && (x0 + 32 < WW);

    const float* qbase = g_pwq  + (size_t)b*DIM*NPIX   + (size_t)h*CPH*NPIX;
    const float* kbase = g_pwkv + (size_t)b*2*DIM*NPIX + (size_t)h*CPH*NPIX;

    float G[36], qn[CPH], kn[CPH];
    #pragma unroll
    for (int i = 0; i < 36; i++) G[i] = 0.f;
    #pragma unroll
    for (int i = 0; i < CPH; i++){ qn[i] = 0.f; kn[i] = 0.f; }

    #pragma unroll 1
    for (int t4 = 0; t4 < 4; t4++){
        const int y0   = blockIdx.y*128 + t4*32 + w*4;
        const int ytop = y0 - 1;
        const bool fast = xfast && (ytop >= 0) && (ytop + 5 < HH);

        float ka[CPH][4];
        #pragma unroll
        for (int c6 = 0; c6 < CPH; c6++){
            float o[4];
            winconv<6>(kbase + (size_t)c6*NPIX, x, xm, xp, ytop, fast, &wk[c6*9], o);
            #pragma unroll
            for (int i = 0; i < 4; i++){ ka[c6][i] = o[i]; kn[c6] += o[i]*o[i]; }
        }
        #pragma unroll
        for (int c6 = 0; c6 < CPH; c6++){
            float o[4];
            winconv<6>(qbase + (size_t)c6*NPIX, x, xm, xp, ytop, fast, &wq[c6*9], o);
            #pragma unroll
            for (int i = 0; i < 4; i++) qn[c6] += o[i]*o[i];
            #pragma unroll
            for (int d6 = 0; d6 < CPH; d6++)
                G[c6*CPH + d6] += o[0]*ka[d6][0] + o[1]*ka[d6][1]
                                + o[2]*ka[d6][2] + o[3]*ka[d6][3];
        }
    }

    #pragma unroll
    for (int j = 0; j < 36; j++){
        float v = G[j];
        #pragma unroll
        for (int o = 16; o; o >>= 1) v += __shfl_xor_sync(0xffffffffu, v, o);
        if (lane == 0) atomicAdd(&accs[j], v);
    }
    #pragma unroll
    for (int j = 0; j < CPH; j++){
        float v = qn[j];
        #pragma unroll
        for (int o = 16; o; o >>= 1) v += __shfl_xor_sync(0xffffffffu, v, o);
        if (lane == 0) atomicAdd(&accs[36 + j], v);
        float u = kn[j];
        #pragma unroll
        for (int o = 16; o; o >>= 1) u += __shfl_xor_sync(0xffffffffu, u, o);
        if (lane == 0) atomicAdd(&accs[42 + j], u);
    }
    __syncthreads();
    if (tid < 48) atomicAdd(&g_acc[(b*HEADS + h)*48 + tid], accs[tid]);
}

// softmax + fold Wout -> Meff[b] (48x48)
__global__ void attn_kernel(const float* __restrict__ Wout,
                            const float* __restrict__ temp){
    __shared__ float attn_s[BATCH*HEADS*36];
    int t = threadIdx.x;
    if (t < BATCH*HEADS*CPH){
        int b  = t/(HEADS*CPH);
        int h  = (t/CPH)%HEADS;
        int c6 = t%CPH;
        const float* a = g_acc + (b*HEADS + h)*48;
        float qnorm = fmaxf(sqrtf(a[36 + c6]), 1e-12f);
        float s[CPH];
        float mx = -1e30f;
        #pragma unroll
        for (int d6 = 0; d6 < CPH; d6++){
            float knorm = fmaxf(sqrtf(a[42 + d6]), 1e-12f);
            float v = a[c6*CPH + d6] / (qnorm*knorm) * temp[h];
            s[d6] = v; mx = fmaxf(mx, v);
        }
        float sum = 0.f;
        #pragma unroll
        for (int d6 = 0; d6 < CPH; d6++){ s[d6] = expf(s[d6]-mx); sum += s[d6]; }
        float inv = 1.f/sum;
        #pragma unroll
        for (int d6 = 0; d6 < CPH; d6++)
            attn_s[(b*HEADS + h)*36 + c6*CPH + d6] = s[d6]*inv;
    }
    __syncthreads();
    for (int e = t; e < BATCH*DIM*DIM; e += blockDim.x){
        int b = e/(DIM*DIM), rem = e%(DIM*DIM), o = rem/DIM, d = rem%DIM;
        int h = d/CPH, d6 = d%CPH;
        float s = 0.f;
        #pragma unroll
        for (int c6 = 0; c6 < CPH; c6++)
            s += Wout[o*DIM + h*CPH + c6] * attn_s[(b*HEADS + h)*36 + c6*CPH + d6];
        g_meff[e] = s;
    }
}

// fused: v = dw3x3(pwkv_hi) into smem tile (upfront-window loads), then out = Meff[b] * v.
__global__ __launch_bounds__(256, 2) void vout_kernel(const float* __restrict__ Wkv2,
                                                      float* __restrict__ out){
    extern __shared__ char smraw[];
    unsigned long long* wm = reinterpret_cast<unsigned long long*>(smraw);      // 48*48 u64
    float* v_s = reinterpret_cast<float*>(smraw + DIM*DIM*8);                   // 48*256 f32
    float* wv  = v_s + DIM*256;                                                 // 48*9 f32

    const int tid = threadIdx.x;
    const int b   = blockIdx.z;
    for (int t = tid; t < DIM*DIM; t += 256){
        float m = g_meff[b*DIM*DIM + t];
        wm[t] = pk2(m, m);
    }
    for (int t = tid; t < DIM*9; t += 256)
        wv[t] = Wkv2[(DIM + t/9)*27 + 9 + (t%9)];
    __syncthreads();

    const int lane = tid & 31;
    const int w    = tid >> 5;
    const int x0   = blockIdx.x*32;
    const int x    = x0 + lane;
    const int yb   = blockIdx.y*8;
    const bool xm = (x > 0), xp = (x < WW-1);
    const bool fast = (x0 > 0) && (x0 + 32 < WW) && (yb > 0) && (yb + 9 < HH);

    const float* vbase = g_pwkv + (size_t)b*2*DIM*NPIX + (size_t)DIM*NPIX;
    #pragma unroll
    for (int c6 = 0; c6 < CPH; c6++){
        int c = w*CPH + c6;
        float o[8];
        winconv<10>(vbase + (size_t)c*NPIX, x, xm, xp, yb - 1, fast, &wv[c*9], o);
        #pragma unroll
        for (int i = 0; i < 8; i++)
            v_s[c*256 + i*32 + lane] = o[i];
    }
    __syncthreads();

    unsigned long long acc[CPH][4];
    #pragma unroll
    for (int j = 0; j < CPH; j++){
        acc[j][0]=0ull; acc[j][1]=0ull; acc[j][2]=0ull; acc[j][3]=0ull;
    }
    #pragma unroll 4
    for (int d = 0; d < DIM; d++){
        const float4* vp = reinterpret_cast<const float4*>(v_s + d*256);
        float4 a  = vp[lane];
        float4 bq = vp[lane + 32];
        unsigned long long a01 = pk2(a.x,  a.y ), a23 = pk2(a.z,  a.w );
        unsigned long long b01 = pk2(bq.x, bq.y), b23 = pk2(bq.z, bq.w);
        #pragma unroll
        for (int j = 0; j < CPH; j++){
            unsigned long long ww = wm[(w*CPH + j)*DIM + d];
            fma2(acc[j][0], a01, ww);
            fma2(acc[j][1], a23, ww);
            fma2(acc[j][2], b01, ww);
            fma2(acc[j][3], b23, ww);
        }
    }

    #pragma unroll
    for (int j = 0; j < CPH; j++){
        int oc = w*CPH + j;
        float* op = out + ((size_t)(b*DIM + oc))*NPIX;
        int px0 = 4*lane;
        int px1 = 128 + 4*lane;
        float2 l0 = unpk(acc[j][0]), h0 = unpk(acc[j][1]);
        float2 l1 = unpk(acc[j][2]), h1 = unpk(acc[j][3]);
        *reinterpret_cast<float4*>(op + (size_t)(yb + (px0>>5))*WW + x0 + (px0&31)) =
            make_float4(l0.x, l0.y, h0.x, h0.y);
        *reinterpret_cast<float4*>(op + (size_t)(yb + (px1>>5))*WW + x0 + (px1&31)) =
            make_float4(l1.x, l1.y, h1.x, h1.y);
    }
}

// ---------------- launch ----------------
extern "C" void kernel_launch(void* const* d_in, const int* in_sizes, int n_in,
                              void* d_out, int out_size){
    const float* img  = (const float*)d_in[0];
    const float* evs  = (const float*)d_in[1];
    const float* Wq1  = (const float*)d_in[2];
    const float* Wq2  = (const float*)d_in[3];
    const float* Wkv1 = (const float*)d_in[4];
    const float* Wkv2 = (const float*)d_in[5];
    const float* Wout = (const float*)d_in[6];
    const float* temp = (const float*)d_in[7];
    float* out = (float*)d_out;

    float *pwq, *pwkv;
    cudaGetSymbolAddress((void**)&pwq,  g_pwq);
    cudaGetSymbolAddress((void**)&pwkv, g_pwkv);

    static cudaStream_t s2 = nullptr;
    static cudaEvent_t  evF = nullptr, evJ = nullptr;
    if (s2 == nullptr){
        cudaStreamCreateWithFlags(&s2, cudaStreamNonBlocking);
        cudaEventCreateWithFlags(&evF, cudaEventDisableTiming);
        cudaEventCreateWithFlags(&evJ, cudaEventDisableTiming);
    }

    size_t smem_vout = (size_t)DIM*DIM*8 + (size_t)DIM*256*4 + (size_t)DIM*9*4; // 69312
    cudaFuncSetAttribute(vout_kernel, cudaFuncAttributeMaxDynamicSharedMemorySize, (int)smem_vout);

    zero_acc_kernel<<<3, 256>>>();

    // fork: img pointwise (96 oc as two halves) on s2, evs pointwise on main
    cudaEventRecord(evF, 0);
    cudaStreamWaitEvent(s2, evF, 0);

    dim3 gimg(NPIX/256, BATCH, 2);
    pw_cp_kernel<<<gimg, 256, 0, s2>>>(img, Wkv1, pwkv, DIM, 2*DIM);

    dim3 gevs(NPIX/256, BATCH, 1);
    pw_cp_kernel<<<gevs, 256>>>(evs, Wq1, pwq, DIM, DIM);

    // join
    cudaEventRecord(evJ, s2);
    cudaStreamWaitEvent(0, evJ, 0);

    dim3 gqk(WW/32, HH/128, BATCH*HEADS);
    qk_gram_kernel<<<gqk, 256>>>(Wq2, Wkv2);

    attn_kernel<<<1, 256>>>(Wout, temp);

    dim3 gvo(WW/32, HH/8, BATCH);
    vout_kernel<<<gvo, 256, smem_vout>>>(Wkv2, out);
}

// round 7
// speedup vs baseline: 2.2664x; 1.0001x over previous
#include <cuda_runtime.h>
#include <math.h>

#define BATCH 2
#define DIM   48
#define HEADS 8
#define CPH   6
#define HH    384
#define WW    384
#define NPIX  (HH*WW)

// ---------------- scratch ----------------
__device__ float g_pwq [BATCH*DIM*NPIX];      // 56.6 MB
__device__ float g_pwkv[BATCH*2*DIM*NPIX];    // 113 MB (k: ch 0..47, v: ch 48..95)
__device__ float g_v   [BATCH*DIM*NPIX];      // 56.6 MB (dw-conv'd v)
__device__ float g_acc [BATCH*HEADS*48];      // 36 Gram + 6 |q|^2 + 6 |k|^2
__device__ float g_meff[BATCH*DIM*DIM];

// ---------------- packed f32x2 ----------------
__device__ __forceinline__ unsigned long long pk2(float lo, float hi){
    unsigned long long r;
    asm("mov.b64 %0, {%1,%2};" : "=l"(r) : "f"(lo), "f"(hi));
    return r;
}
__device__ __forceinline__ void fma2(unsigned long long &d,
                                     unsigned long long a,
                                     unsigned long long b){
    asm("fma.rn.f32x2 %0, %1, %2, %3;" : "=l"(d) : "l"(a), "l"(b), "l"(d));
}
__device__ __forceinline__ float2 unpk(unsigned long long v){
    float lo, hi;
    asm("mov.b64 {%0,%1}, %2;" : "=f"(lo), "=f"(hi) : "l"(v));
    return make_float2(lo, hi);
}

__device__ __forceinline__ void cpa16(unsigned int dst, const float* src){
    asm volatile("cp.async.cg.shared.global [%0], [%1], 16;" :: "r"(dst), "l"(src) : "memory");
}
__device__ __forceinline__ void cpa_commit(){
    asm volatile("cp.async.commit_group;" ::: "memory");
}
template<int N>
__device__ __forceinline__ void cpa_wait(){
    asm volatile("cp.async.wait_group %0;" :: "n"(N) : "memory");
}

// Load an R-row x 3-col window upfront (independent LDGs, MLP=3R) and produce
// R-2 conv outputs. fast => no bounds handling (interior block).
template<int R>
__device__ __forceinline__ void winconv(const float* __restrict__ chan, int x,
                                        bool xm, bool xp, int ytop, bool fast,
                                        const float* __restrict__ wr, float* out){
    float v[R][3];
    if (fast){
        const float* rp = chan + (size_t)ytop*WW + x;
        #pragma unroll
        for (int r = 0; r < R; r++){
            v[r][0] = __ldg(rp + r*WW - 1);
            v[r][1] = __ldg(rp + r*WW    );
            v[r][2] = __ldg(rp + r*WW + 1);
        }
    } else {
        int xl = max(x-1, 0), xr = min(x+1, WW-1);
        #pragma unroll
        for (int r = 0; r < R; r++){
            int yy = ytop + r; bool yok = (yy >= 0 && yy < HH);
            const float* rp = chan + (size_t)(yok ? yy : 0)*WW;
            v[r][0] = (yok && xm) ? __ldg(rp + xl) : 0.f;
            v[r][1] =  yok        ? __ldg(rp + x ) : 0.f;
            v[r][2] = (yok && xp) ? __ldg(rp + xr) : 0.f;
        }
    }
    #pragma unroll
    for (int i = 0; i < R-2; i++){
        out[i] = wr[0]*v[i  ][0] + wr[1]*v[i  ][1] + wr[2]*v[i  ][2]
               + wr[3]*v[i+1][0] + wr[4]*v[i+1][1] + wr[5]*v[i+1][2]
               + wr[6]*v[i+2][0] + wr[7]*v[i+2][1] + wr[8]*v[i+2][2];
    }
}

// ---------------- kernels ----------------
__global__ void zero_acc_kernel(){
    int t = blockIdx.x*blockDim.x + threadIdx.x;
    if (t < BATCH*HEADS*48) g_acc[t] = 0.f;
}

// 1x1 conv as GEMM with cp.async double-buffered input staging.
// Block: 256 threads, 256 px, 48 oc (oc-half = blockIdx.z + zbase).
// Weights at W + b*wStride + half*DIM*DIM (wStride!=0 => per-batch weights).
__global__ __launch_bounds__(256, 2) void pw_cp_kernel(const float* __restrict__ in,
                                                       const float* __restrict__ W,
                                                       float* __restrict__ out,
                                                       int inBC, int outBC,
                                                       int zbase, int wStride){
    __shared__ unsigned long long ws[DIM*DIM];   // 18 KB
    __shared__ float xs[2][8*256];               // 16 KB

    const int b  = blockIdx.y;
    const int zh = blockIdx.z + zbase;
    const float* Wb = W + b*wStride + zh*DIM*DIM;
    for (int t = threadIdx.x; t < DIM*DIM; t += 256){
        float w = Wb[t];
        ws[t] = pk2(w, w);
    }

    const int tid  = threadIdx.x;
    const int base = blockIdx.x*256;
    const float* inp = in + (size_t)b*inBC*NPIX + base;
    const unsigned int xsu =
        (unsigned int)__cvta_generic_to_shared(&xs[0][0]);

    auto issue = [&](int c, int buf){
        #pragma unroll
        for (int r = 0; r < 2; r++){
            int e   = tid + r*256;
            int icl = e >> 6;
            int q   = e & 63;
            cpa16(xsu + (unsigned int)((buf*2048 + icl*256 + q*4)*4),
                  inp + (size_t)(c*8 + icl)*NPIX + q*4);
        }
        cpa_commit();
    };

    issue(0, 0);

    const int pxq = tid & 31;
    const int ocg = tid >> 5;

    unsigned long long acc[CPH][4];
    #pragma unroll
    for (int j = 0; j < CPH; j++){
        acc[j][0]=0ull; acc[j][1]=0ull; acc[j][2]=0ull; acc[j][3]=0ull;
    }

    #pragma unroll
    for (int c = 0; c < 6; c++){
        if (c < 5) issue(c+1, (c+1)&1);
        if (c < 5) cpa_wait<1>(); else cpa_wait<0>();
        __syncthreads();

        const float* xb = &xs[c&1][0];
        #pragma unroll
        for (int icl = 0; icl < 8; icl++){
            const float4* xp = reinterpret_cast<const float4*>(xb + icl*256 + pxq*8);
            float4 xa = xp[0];
            float4 xc = xp[1];
            unsigned long long a01 = pk2(xa.x, xa.y), a23 = pk2(xa.z, xa.w);
            unsigned long long b01 = pk2(xc.x, xc.y), b23 = pk2(xc.z, xc.w);
            #pragma unroll
            for (int j = 0; j < CPH; j++){
                unsigned long long w = ws[(ocg*CPH + j)*DIM + c*8 + icl];
                fma2(acc[j][0], a01, w);
                fma2(acc[j][1], a23, w);
                fma2(acc[j][2], b01, w);
                fma2(acc[j][3], b23, w);
            }
        }
        __syncthreads();
    }

    float* op = out + (size_t)b*outBC*NPIX + base + pxq*8;
    #pragma unroll
    for (int j = 0; j < CPH; j++){
        float* o = op + (size_t)(zh*DIM + ocg*CPH + j)*NPIX;
        float2 l0 = unpk(acc[j][0]), h0 = unpk(acc[j][1]);
        float2 l1 = unpk(acc[j][2]), h1 = unpk(acc[j][3]);
        *reinterpret_cast<float4*>(o)     = make_float4(l0.x, l0.y, h0.x, h0.y);
        *reinterpret_cast<float4*>(o + 4) = make_float4(l1.x, l1.y, h1.x, h1.y);
    }
}

// q,k depthwise 3x3 + Gram/norm. One (b,h) per block; block covers 32x128 px.
__global__ __launch_bounds__(256, 2) void qk_gram_kernel(const float* __restrict__ Wq2,
                                                         const float* __restrict__ Wkv2){
    __shared__ float wq[CPH*9], wk[CPH*9];
    __shared__ float accs[48];
    const int tid = threadIdx.x;
    const int bh  = blockIdx.z;
    const int b   = bh >> 3, h = bh & 7;
    if (tid < CPH*9){
        int c6 = tid/9, t = tid%9;
        wq[tid] = Wq2[(h*CPH + c6)*27 + 9 + t];
    } else if (tid >= 64 && tid < 64 + CPH*9){
        int e = tid - 64, c6 = e/9, t = e%9;
        wk[e] = Wkv2[(h*CPH + c6)*27 + 9 + t];
    } else if (tid >= 128 && tid < 176){
        accs[tid - 128] = 0.f;
    }
    __syncthreads();

    const int lane = tid & 31;
    const int w    = tid >> 5;
    const int x0   = blockIdx.x*32;
    const int x    = x0 + lane;
    const bool xm = (x > 0), xp = (x < WW-1);
    const bool xfast = (x0 > 0) && (x0 + 32 < WW);

    const float* qbase = g_pwq  + (size_t)b*DIM*NPIX   + (size_t)h*CPH*NPIX;
    const float* kbase = g_pwkv + (size_t)b*2*DIM*NPIX + (size_t)h*CPH*NPIX;

    float G[36], qn[CPH], kn[CPH];
    #pragma unroll
    for (int i = 0; i < 36; i++) G[i] = 0.f;
    #pragma unroll
    for (int i = 0; i < CPH; i++){ qn[i] = 0.f; kn[i] = 0.f; }

    #pragma unroll 1
    for (int t4 = 0; t4 < 4; t4++){
        const int y0   = blockIdx.y*128 + t4*32 + w*4;
        const int ytop = y0 - 1;
        const bool fast = xfast && (ytop >= 0) && (ytop + 5 < HH);

        float ka[CPH][4];
        #pragma unroll
        for (int c6 = 0; c6 < CPH; c6++){
            float o[4];
            winconv<6>(kbase + (size_t)c6*NPIX, x, xm, xp, ytop, fast, &wk[c6*9], o);
            #pragma unroll
            for (int i = 0; i < 4; i++){ ka[c6][i] = o[i]; kn[c6] += o[i]*o[i]; }
        }
        #pragma unroll
        for (int c6 = 0; c6 < CPH; c6++){
            float o[4];
            winconv<6>(qbase + (size_t)c6*NPIX, x, xm, xp, ytop, fast, &wq[c6*9], o);
            #pragma unroll
            for (int i = 0; i < 4; i++) qn[c6] += o[i]*o[i];
            #pragma unroll
            for (int d6 = 0; d6 < CPH; d6++)
                G[c6*CPH + d6] += o[0]*ka[d6][0] + o[1]*ka[d6][1]
                                + o[2]*ka[d6][2] + o[3]*ka[d6][3];
        }
    }

    #pragma unroll
    for (int j = 0; j < 36; j++){
        float v = G[j];
        #pragma unroll
        for (int o = 16; o; o >>= 1) v += __shfl_xor_sync(0xffffffffu, v, o);
        if (lane == 0) atomicAdd(&accs[j], v);
    }
    #pragma unroll
    for (int j = 0; j < CPH; j++){
        float v = qn[j];
        #pragma unroll
        for (int o = 16; o; o >>= 1) v += __shfl_xor_sync(0xffffffffu, v, o);
        if (lane == 0) atomicAdd(&accs[36 + j], v);
        float u = kn[j];
        #pragma unroll
        for (int o = 16; o; o >>= 1) u += __shfl_xor_sync(0xffffffffu, u, o);
        if (lane == 0) atomicAdd(&accs[42 + j], u);
    }
    __syncthreads();
    if (tid < 48) atomicAdd(&g_acc[(b*HEADS + h)*48 + tid], accs[tid]);
}

// softmax + fold Wout -> Meff[b] (48x48)
__global__ void attn_kernel(const float* __restrict__ Wout,
                            const float* __restrict__ temp){
    __shared__ float attn_s[BATCH*HEADS*36];
    int t = threadIdx.x;
    if (t < BATCH*HEADS*CPH){
        int b  = t/(HEADS*CPH);
        int h  = (t/CPH)%HEADS;
        int c6 = t%CPH;
        const float* a = g_acc + (b*HEADS + h)*48;
        float qnorm = fmaxf(sqrtf(a[36 + c6]), 1e-12f);
        float s[CPH];
        float mx = -1e30f;
        #pragma unroll
        for (int d6 = 0; d6 < CPH; d6++){
            float knorm = fmaxf(sqrtf(a[42 + d6]), 1e-12f);
            float v = a[c6*CPH + d6] / (qnorm*knorm) * temp[h];
            s[d6] = v; mx = fmaxf(mx, v);
        }
        float sum = 0.f;
        #pragma unroll
        for (int d6 = 0; d6 < CPH; d6++){ s[d6] = expf(s[d6]-mx); sum += s[d6]; }
        float inv = 1.f/sum;
        #pragma unroll
        for (int d6 = 0; d6 < CPH; d6++)
            attn_s[(b*HEADS + h)*36 + c6*CPH + d6] = s[d6]*inv;
    }
    __syncthreads();
    for (int e = t; e < BATCH*DIM*DIM; e += blockDim.x){
        int b = e/(DIM*DIM), rem = e%(DIM*DIM), o = rem/DIM, d = rem%DIM;
        int h = d/CPH, d6 = d%CPH;
        float s = 0.f;
        #pragma unroll
        for (int c6 = 0; c6 < CPH; c6++)
            s += Wout[o*DIM + h*CPH + c6] * attn_s[(b*HEADS + h)*36 + c6*CPH + d6];
        g_meff[e] = s;
    }
}

// depthwise 3x3 for v channels -> g_v (independent of attention; runs on side stream)
__global__ __launch_bounds__(256, 2) void v_conv_kernel(const float* __restrict__ Wkv2){
    __shared__ float wv[DIM*9];
    const int tid = threadIdx.x;
    for (int t = tid; t < DIM*9; t += 256)
        wv[t] = Wkv2[(DIM + t/9)*27 + 9 + (t%9)];
    __syncthreads();

    const int lane = tid & 31;
    const int w    = tid >> 5;
    const int b    = blockIdx.z;
    const int x0   = blockIdx.x*32;
    const int x    = x0 + lane;
    const int yb   = blockIdx.y*8;
    const bool xm = (x > 0), xp = (x < WW-1);
    const bool fast = (x0 > 0) && (x0 + 32 < WW) && (yb > 0) && (yb + 9 < HH);

    const float* vbase = g_pwkv + (size_t)b*2*DIM*NPIX + (size_t)DIM*NPIX;
    float* vo = g_v + (size_t)b*DIM*NPIX;
    #pragma unroll
    for (int c6 = 0; c6 < CPH; c6++){
        int c = w*CPH + c6;
        float o[8];
        winconv<10>(vbase + (size_t)c*NPIX, x, xm, xp, yb - 1, fast, &wv[c*9], o);
        #pragma unroll
        for (int i = 0; i < 8; i++)
            vo[(size_t)c*NPIX + (size_t)(yb + i)*WW + x] = o[i];
    }
}

// ---------------- launch ----------------
extern "C" void kernel_launch(void* const* d_in, const int* in_sizes, int n_in,
                              void* d_out, int out_size){
    const float* img  = (const float*)d_in[0];
    const float* evs  = (const float*)d_in[1];
    const float* Wq1  = (const float*)d_in[2];
    const float* Wq2  = (const float*)d_in[3];
    const float* Wkv1 = (const float*)d_in[4];
    const float* Wkv2 = (const float*)d_in[5];
    const float* Wout = (const float*)d_in[6];
    const float* temp = (const float*)d_in[7];
    float* out = (float*)d_out;

    float *pwq, *pwkv, *vbuf, *meff;
    cudaGetSymbolAddress((void**)&pwq,  g_pwq);
    cudaGetSymbolAddress((void**)&pwkv, g_pwkv);
    cudaGetSymbolAddress((void**)&vbuf, g_v);
    cudaGetSymbolAddress((void**)&meff, g_meff);

    static cudaStream_t s2 = nullptr;
    static cudaEvent_t  evF = nullptr, evK = nullptr, evV = nullptr;
    if (s2 == nullptr){
        cudaStreamCreateWithFlags(&s2, cudaStreamNonBlocking);
        cudaEventCreateWithFlags(&evF, cudaEventDisableTiming);
        cudaEventCreateWithFlags(&evK, cudaEventDisableTiming);
        cudaEventCreateWithFlags(&evV, cudaEventDisableTiming);
    }

    zero_acc_kernel<<<3, 256>>>();

    // fork
    cudaEventRecord(evF, 0);
    cudaStreamWaitEvent(s2, evF, 0);

    dim3 gpw(NPIX/256, BATCH, 1);
    // stream B: k-half of img pw, then v-half + v depthwise conv
    pw_cp_kernel<<<gpw, 256, 0, s2>>>(img, Wkv1, pwkv, DIM, 2*DIM, 0, 0);
    cudaEventRecord(evK, s2);
    pw_cp_kernel<<<gpw, 256, 0, s2>>>(img, Wkv1, pwkv, DIM, 2*DIM, 1, 0);
    dim3 gvc(WW/32, HH/8, BATCH);
    v_conv_kernel<<<gvc, 256, 0, s2>>>(Wkv2);
    cudaEventRecord(evV, s2);

    // main: evs pw, then qk (needs k-half), attn, final GEMM (needs g_v)
    pw_cp_kernel<<<gpw, 256>>>(evs, Wq1, pwq, DIM, DIM, 0, 0);
    cudaStreamWaitEvent(0, evK, 0);

    dim3 gqk(WW/32, HH/128, BATCH*HEADS);
    qk_gram_kernel<<<gqk, 256>>>(Wq2, Wkv2);

    attn_kernel<<<1, 256>>>(Wout, temp);

    cudaStreamWaitEvent(0, evV, 0);
    pw_cp_kernel<<<gpw, 256>>>(vbuf, meff, out, DIM, DIM, 0, DIM*DIM);
}